// round 6
// baseline (speedup 1.0000x reference)
#include <cuda_runtime.h>
#include <cuda_bf16.h>
#include <math.h>
#include <cstdint>

// ---------------------------------------------------------------------------
// MSMDDeformRegionAttn  (N=4, Lq=300, C=256, H=8, Dh=32, L=4, P=4, ROI=7)
//
//   1. value = input_flatten @ Wv + bv            (79788 x 256 x 256)  HMMA
//   2. ROI-align 7x7 on level-0 feature map -> roi_flat
//   3. pw = roi_flat @ [Wp | Ww]                  (1200 x 12544 x 384) HMMA
//   4. tanh offsets + softmax weights + deformable bilinear gather
//   5. out = att @ Wo + bo                        (1200 x 256 x 256)   FFMA2
//
// Big GEMMs: warp-level mma.sync m16n8k16 bf16 (baseline PTX, no arch suffix)
// with 3-way bf16 split of each fp32 operand and 6 cross-product MMAs
// -> fp32-grade accuracy (residual ~2^-25) on the tensor pipe.
// ---------------------------------------------------------------------------

#define NB      4
#define LQ      300
#define NQ      (NB * LQ)          // 1200
#define CDIM    256
#define NHEADS  8
#define DH      32
#define NLVL    4
#define NPTS    4
#define ROI     7
#define LEN_IN  19947
#define ROI_DIM (ROI * ROI * CDIM) // 12544
#define NPW     384                // 256 (Wp) + 128 (Ww)
#define SPLITK  14
#define KCHUNK  (ROI_DIM / SPLITK) // 896 = 28 * 32

// ------------------------- scratch (static device mem) ---------------------
__device__ float g_value[(size_t)NB * LEN_IN * CDIM];          // 81.7 MB
__device__ float g_roi[(size_t)NQ * ROI_DIM];                  // 60.2 MB
__device__ float g_part[(size_t)SPLITK * NQ * NPW];            // 25.8 MB
__device__ float g_pw[(size_t)NQ * NPW];
__device__ float g_att[(size_t)NQ * CDIM];
// pre-transposed + 3-way-split weights (bf16 planes, layout [n][k])
__device__ __nv_bfloat16 g_btv[(size_t)3 * CDIM * CDIM];       // 0.4 MB
__device__ __nv_bfloat16 g_btpw[(size_t)3 * NPW * ROI_DIM];    // 28.9 MB

// --------------------------- bf16 3-way split -------------------------------
__device__ __forceinline__ unsigned short bf16rn_rem(float x, float& rem)
{
    __nv_bfloat16 h = __float2bfloat16_rn(x);
    unsigned short hb = ((__nv_bfloat16_raw)h).x;
    rem = x - __uint_as_float((uint32_t)hb << 16);
    return hb;
}
__device__ __forceinline__ unsigned short bf16rn(float x)
{
    __nv_bfloat16 h = __float2bfloat16_rn(x);
    return ((__nv_bfloat16_raw)h).x;
}

// --------------------------- MMA primitives --------------------------------
__device__ __forceinline__ void mma_bf16(float* d, const uint32_t* a,
                                         const uint32_t* b)
{
    asm volatile(
        "mma.sync.aligned.m16n8k16.row.col.f32.bf16.bf16.f32 "
        "{%0,%1,%2,%3}, {%4,%5,%6,%7}, {%8,%9}, {%0,%1,%2,%3};"
        : "+f"(d[0]), "+f"(d[1]), "+f"(d[2]), "+f"(d[3])
        : "r"(a[0]), "r"(a[1]), "r"(a[2]), "r"(a[3]), "r"(b[0]), "r"(b[1]));
}
__device__ __forceinline__ void ldsm4(uint32_t* r, uint32_t addr)
{
    asm volatile(
        "ldmatrix.sync.aligned.m8n8.x4.shared.b16 {%0,%1,%2,%3}, [%4];"
        : "=r"(r[0]), "=r"(r[1]), "=r"(r[2]), "=r"(r[3]) : "r"(addr));
}
__device__ __forceinline__ uint32_t smem_u32(const void* p)
{
    uint32_t a;
    asm("{ .reg .u64 t; cvta.to.shared.u64 t, %1; cvt.u32.u64 %0, t; }"
        : "=r"(a) : "l"(p));
    return a;
}

// ------------------------- HMMA split-bf16 GEMM -----------------------------
// C[m0:, n0:] = A(fp32, row-major lda) @ Bt^T where Bt is pre-transposed,
// pre-split bf16: Bt[plane][n][k] (row stride ldbK, plane stride bPlane).
// Block tile 128x128, BK=32, split-K via blockIdx.z. kChunkTot % 32 == 0.
#define KPAD  40                         // bf16 row stride (80 B) -> no LDSM conflicts
#define PLANE (128 * KPAD)               // elems per plane
#define SM_ELE (6 * PLANE)               // 3 A planes + 3 B planes
#define SM_BYTES (SM_ELE * 2)            // 61440

__global__ __launch_bounds__(256, 2) void mma_gemm(
    const float* __restrict__ A, int lda,
    const __nv_bfloat16* __restrict__ Bt, size_t bPlane, int ldbK,
    float* __restrict__ C, int ldc, long long cSplitStride,
    int M, int kChunkTot, const float* __restrict__ bias)
{
    extern __shared__ __nv_bfloat16 sm[];
    __nv_bfloat16* sA = sm;              // [3][128][KPAD]
    __nv_bfloat16* sB = sm + 3 * PLANE;  // [3][128][KPAD]
    const uint32_t sAu = smem_u32(sA);
    const uint32_t sBu = smem_u32(sB);

    const int tid = threadIdx.x;
    const int lane = tid & 31;
    const int wid = tid >> 5;
    const int warp_m = wid >> 2;         // 0..1 (64 rows each)
    const int warp_n = wid & 3;          // 0..3 (32 cols each)
    const int m0 = blockIdx.y * 128;
    const int n0 = blockIdx.x * 128;
    const int kBase = blockIdx.z * kChunkTot;
    C += (long long)blockIdx.z * cSplitStride;

    // gmem load coords: row = tid/2 (0..127), k-half = (tid&1)*16
    const int row = tid >> 1;
    const int kh = (tid & 1) * 16;
    const bool aval = (m0 + row) < M;
    const float* aRow = A + (size_t)(m0 + row) * lda + kBase + kh;
    const __nv_bfloat16* bRow = Bt + (size_t)(n0 + row) * ldbK + kBase + kh;
    const uint32_t stsOff = (uint32_t)(row * KPAD + kh) * 2;  // byte offset

    // ldmatrix base offsets (bytes), per-thread
    const uint32_t aRowSel = (uint32_t)((warp_m * 64 + (lane & 15)) * KPAD +
                                        ((lane >> 4) << 3)) * 2;
    const uint32_t bRowSel = (uint32_t)((warp_n * 32 + ((lane >> 4) << 3) +
                                         (lane & 7)) * KPAD +
                                        (((lane >> 3) & 1) << 3)) * 2;

    float acc[4][4][4];
#pragma unroll
    for (int i = 0; i < 4; i++)
#pragma unroll
        for (int j = 0; j < 4; j++)
#pragma unroll
            for (int e = 0; e < 4; e++) acc[i][j][e] = 0.f;

    const int nIter = kChunkTot / 32;
    for (int it = 0; it < nIter; ++it) {
        // ---- A: load 16 fp32, split into 3 bf16 planes, STS ----
        {
            float f[16];
            if (aval) {
#pragma unroll
                for (int j = 0; j < 4; j++) {
                    float4 v = *(const float4*)(aRow + it * 32 + j * 4);
                    f[j * 4 + 0] = v.x; f[j * 4 + 1] = v.y;
                    f[j * 4 + 2] = v.z; f[j * 4 + 3] = v.w;
                }
            } else {
#pragma unroll
                for (int e = 0; e < 16; e++) f[e] = 0.f;
            }
            unsigned short h0[16], h1[16], h2[16];
#pragma unroll
            for (int e = 0; e < 16; e++) {
                float r1, r2;
                h0[e] = bf16rn_rem(f[e], r1);
                h1[e] = bf16rn_rem(r1, r2);
                h2[e] = bf16rn(r2);
            }
            unsigned short* hp[3] = {h0, h1, h2};
#pragma unroll
            for (int p = 0; p < 3; p++) {
                unsigned short* h = hp[p];
#pragma unroll
                for (int half = 0; half < 2; half++) {
                    uint4 q;
                    q.x = (uint32_t)h[half*8+0] | ((uint32_t)h[half*8+1] << 16);
                    q.y = (uint32_t)h[half*8+2] | ((uint32_t)h[half*8+3] << 16);
                    q.z = (uint32_t)h[half*8+4] | ((uint32_t)h[half*8+5] << 16);
                    q.w = (uint32_t)h[half*8+6] | ((uint32_t)h[half*8+7] << 16);
                    *(uint4*)((char*)sA + p * PLANE * 2 + stsOff + half * 16) = q;
                }
            }
        }
        // ---- B: pre-split bf16 planes, copy 16 bf16 per plane ----
#pragma unroll
        for (int p = 0; p < 3; p++) {
            uint4 v0 = *(const uint4*)(bRow + p * bPlane + it * 32);
            uint4 v1 = *(const uint4*)(bRow + p * bPlane + it * 32 + 8);
            *(uint4*)((char*)sB + p * PLANE * 2 + stsOff)      = v0;
            *(uint4*)((char*)sB + p * PLANE * 2 + stsOff + 16) = v1;
        }
        __syncthreads();

        // ---- compute: 2 k16-steps x 6 split-products x 16 mma ----
#pragma unroll
        for (int k16 = 0; k16 < 2; k16++) {
            const uint32_t kOff = (uint32_t)(k16 * 16) * 2;
#pragma unroll
            for (int pa = 0; pa < 3; pa++) {
                uint32_t af[4][4];
#pragma unroll
                for (int i = 0; i < 4; i++)
                    ldsm4(af[i], sAu + pa * PLANE * 2 + aRowSel + kOff +
                                 (uint32_t)(i * 16 * KPAD) * 2);
                const int npb = 3 - pa;   // pa=0:{0,1,2} pa=1:{0,1} pa=2:{0}
                for (int pb = 0; pb < npb; pb++) {
                    uint32_t bf[4][2];
#pragma unroll
                    for (int jj = 0; jj < 2; jj++) {
                        uint32_t r[4];
                        ldsm4(r, sBu + pb * PLANE * 2 + bRowSel + kOff +
                                 (uint32_t)(jj * 16 * KPAD) * 2);
                        bf[jj*2][0] = r[0]; bf[jj*2][1] = r[1];
                        bf[jj*2+1][0] = r[2]; bf[jj*2+1][1] = r[3];
                    }
#pragma unroll
                    for (int i = 0; i < 4; i++)
#pragma unroll
                        for (int j = 0; j < 4; j++)
                            mma_bf16(acc[i][j], af[i], bf[j]);
                }
            }
        }
        __syncthreads();
    }

    // ---- epilogue: register accumulators -> gmem ----
    const int colBase = n0 + warp_n * 32 + (lane & 3) * 2;
    const int rowBase = m0 + warp_m * 64 + (lane >> 2);
#pragma unroll
    for (int i = 0; i < 4; i++) {
#pragma unroll
        for (int j = 0; j < 4; j++) {
            const int gc = colBase + j * 8;
            float bx = 0.f, by = 0.f;
            if (bias) { bx = bias[gc]; by = bias[gc + 1]; }
            const int r0 = rowBase + i * 16;
            if (r0 < M) {
                float2 v = make_float2(acc[i][j][0] + bx, acc[i][j][1] + by);
                *(float2*)(C + (size_t)r0 * ldc + gc) = v;
            }
            const int r1 = r0 + 8;
            if (r1 < M) {
                float2 v = make_float2(acc[i][j][2] + bx, acc[i][j][3] + by);
                *(float2*)(C + (size_t)r1 * ldc + gc) = v;
            }
        }
    }
}

// -------------------- weight transpose + 3-way bf16 split -------------------
// W is [K][N] fp32; out planes are [Ntot][K] bf16, rows offset by rowOff.
__global__ __launch_bounds__(256) void k_tsplit(
    const float* __restrict__ W, int K, int N,
    __nv_bfloat16* __restrict__ out, size_t plane, int rowOff)
{
    __shared__ float t[32][33];
    const int kb = blockIdx.y * 32, nb = blockIdx.x * 32;
    const int c = threadIdx.x & 31, r8 = threadIdx.x >> 5;
#pragma unroll
    for (int i = 0; i < 4; i++)
        t[r8 + i * 8][c] = W[(size_t)(kb + r8 + i * 8) * N + nb + c];
    __syncthreads();
#pragma unroll
    for (int i = 0; i < 4; i++) {
        const int n = nb + r8 + i * 8;
        const int k = kb + c;
        float x = t[c][r8 + i * 8];
        float r1, r2;
        unsigned short h0 = bf16rn_rem(x, r1);
        unsigned short h1 = bf16rn_rem(r1, r2);
        unsigned short h2 = bf16rn(r2);
        size_t o = (size_t)(n + rowOff) * K + k;
        ((unsigned short*)out)[o] = h0;
        ((unsigned short*)out)[plane + o] = h1;
        ((unsigned short*)out)[2 * plane + o] = h2;
    }
}

// ------------------------------ FFMA2 SGEMM (small out GEMM) ----------------
__device__ __forceinline__ void ffma2(unsigned long long& acc,
                                      unsigned long long a, unsigned long long b)
{ asm("fma.rn.f32x2 %0, %1, %2, %0;" : "+l"(acc) : "l"(a), "l"(b)); }
__device__ __forceinline__ unsigned long long pack2(float x)
{ unsigned long long r; asm("mov.b64 %0, {%1, %1};" : "=l"(r) : "f"(x)); return r; }
__device__ __forceinline__ float2 unpack2(unsigned long long v)
{ float2 f; asm("mov.b64 {%0, %1}, %2;" : "=f"(f.x), "=f"(f.y) : "l"(v)); return f; }

#define BM 128
#define BN 128
#define BK8 8
__global__ __launch_bounds__(256, 2) void sgemm128(
    const float* __restrict__ A, int lda,
    const float* __restrict__ B0, int ldb0,
    float* __restrict__ C, int ldc,
    int M, int kChunk, const float* __restrict__ bias)
{
    __shared__ __align__(16) float As[2][BK8][BM + 4];
    __shared__ __align__(16) float Bs[2][BK8][BN + 4];
    const int tid = threadIdx.x;
    const int tx = tid & 15, ty = tid >> 4;
    const int m0 = blockIdx.y * BM;
    const int n0 = blockIdx.x * BN;

    const int ar = tid >> 1, ac = (tid & 1) * 4;
    const int br = tid >> 5, bc = (tid & 31) * 4;
    const bool aval = (m0 + ar) < M;
    const float* Aptr = A + (size_t)(m0 + ar) * lda + ac;
    const float* Bptr = B0 + (size_t)br * ldb0 + n0 + bc;

    unsigned long long acc[8][4];
#pragma unroll
    for (int i = 0; i < 8; i++)
#pragma unroll
        for (int j = 0; j < 4; j++) acc[i][j] = 0ULL;

    float4 aR = make_float4(0.f, 0.f, 0.f, 0.f);
    if (aval) aR = *(const float4*)(Aptr);
    float4 bR = *(const float4*)(Bptr);
    int buf = 0;
    As[buf][ac + 0][ar] = aR.x; As[buf][ac + 1][ar] = aR.y;
    As[buf][ac + 2][ar] = aR.z; As[buf][ac + 3][ar] = aR.w;
    *(float4*)&Bs[buf][br][bc] = bR;
    __syncthreads();

#define COMPUTE(BUF)                                                           \
    {                                                                          \
        _Pragma("unroll")                                                      \
        for (int kk = 0; kk < BK8; kk++) {                                     \
            float4 a0 = *(const float4*)&As[BUF][kk][ty * 4];                  \
            float4 a1 = *(const float4*)&As[BUF][kk][64 + ty * 4];             \
            unsigned long long b0 = *(const unsigned long long*)&Bs[BUF][kk][tx * 4];      \
            unsigned long long b1 = *(const unsigned long long*)&Bs[BUF][kk][tx * 4 + 2];  \
            unsigned long long b2 = *(const unsigned long long*)&Bs[BUF][kk][64 + tx * 4]; \
            unsigned long long b3 = *(const unsigned long long*)&Bs[BUF][kk][64 + tx * 4 + 2]; \
            float a[8] = {a0.x, a0.y, a0.z, a0.w, a1.x, a1.y, a1.z, a1.w};     \
            _Pragma("unroll")                                                  \
            for (int i = 0; i < 8; i++) {                                      \
                unsigned long long ap = pack2(a[i]);                           \
                ffma2(acc[i][0], ap, b0); ffma2(acc[i][1], ap, b1);            \
                ffma2(acc[i][2], ap, b2); ffma2(acc[i][3], ap, b3);            \
            }                                                                  \
        }                                                                      \
    }

    const int nIter = kChunk / BK8;
    for (int it = 1; it < nIter; it++) {
        const int k0 = it * BK8;
        float4 aN = make_float4(0.f, 0.f, 0.f, 0.f);
        if (aval) aN = *(const float4*)(Aptr + k0);
        float4 bN = *(const float4*)(Bptr + (size_t)k0 * ldb0);
        COMPUTE(buf);
        const int nbuf = buf ^ 1;
        As[nbuf][ac + 0][ar] = aN.x; As[nbuf][ac + 1][ar] = aN.y;
        As[nbuf][ac + 2][ar] = aN.z; As[nbuf][ac + 3][ar] = aN.w;
        *(float4*)&Bs[nbuf][br][bc] = bN;
        __syncthreads();
        buf = nbuf;
    }
    COMPUTE(buf);
#undef COMPUTE

#pragma unroll
    for (int i = 0; i < 8; i++) {
        const int gm = m0 + ((i < 4) ? (ty * 4 + i) : (64 + ty * 4 + i - 4));
        if (gm >= M) continue;
#pragma unroll
        for (int j = 0; j < 4; j++) {
            const int gn = n0 + ((j < 2) ? (tx * 4 + j * 2) : (64 + tx * 4 + (j - 2) * 2));
            float2 v = unpack2(acc[i][j]);
            if (bias) { v.x += bias[gn]; v.y += bias[gn + 1]; }
            C[(size_t)gm * ldc + gn] = v.x;
            C[(size_t)gm * ldc + gn + 1] = v.y;
        }
    }
}

// --------------------------- bilinear helper -------------------------------
__device__ __forceinline__ float bilin(const float* __restrict__ base,
                                       int Hl, int Wl, int stride,
                                       float y, float x)
{
    float fy = floorf(y), fx = floorf(x);
    int y0 = (int)fy, x0 = (int)fx;
    float wy1 = y - fy, wx1 = x - fx;
    float wy0 = 1.f - wy1, wx0 = 1.f - wx1;
    float v = 0.f;
    bool xa = (x0 >= 0) && (x0 < Wl);
    bool xb = (x0 + 1 >= 0) && (x0 + 1 < Wl);
    if (y0 >= 0 && y0 < Hl) {
        if (xa) v += base[(y0 * Wl + x0) * stride] * (wy0 * wx0);
        if (xb) v += base[(y0 * Wl + x0 + 1) * stride] * (wy0 * wx1);
    }
    if (y0 + 1 >= 0 && y0 + 1 < Hl) {
        if (xa) v += base[((y0 + 1) * Wl + x0) * stride] * (wy1 * wx0);
        if (xb) v += base[((y0 + 1) * Wl + x0 + 1) * stride] * (wy1 * wx1);
    }
    return v;
}

// ------------------------------ ROI align ----------------------------------
__global__ __launch_bounds__(256) void k_roi(const float* __restrict__ ref,
                                             const float* __restrict__ value,
                                             float* __restrict__ roi)
{
    int q = blockIdx.x;
    int n = q / LQ;
    int t = threadIdx.x;
    __shared__ float sr[4];
    if (t < 4) sr[t] = ref[(size_t)q * 16 + t];
    __syncthreads();
    const float cx = sr[0], cy = sr[1], w = sr[2], h = sr[3];
    const float x1 = (cx - 0.5f * w) * 150.f - 0.5f;
    const float y1 = (cy - 0.5f * h) * 100.f - 0.5f;
    const float bw = w * 150.f / (float)ROI;
    const float bh = h * 100.f / (float)ROI;
    const float* base = value + (size_t)n * LEN_IN * CDIM + t;
    float* out = roi + (size_t)q * ROI_DIM;
    for (int by = 0; by < ROI; by++) {
        float y = y1 + bh * ((float)by + 0.5f);
        for (int bx = 0; bx < ROI; bx++) {
            float x = x1 + bw * ((float)bx + 0.5f);
            out[(by * ROI + bx) * CDIM + t] = bilin(base, 100, 150, CDIM, y, x);
        }
    }
}

// ------------------------- split-K reduce + bias ----------------------------
__global__ __launch_bounds__(256) void k_reduce(const float* __restrict__ part,
                                                const float* __restrict__ bp,
                                                const float* __restrict__ bw,
                                                float* __restrict__ pw)
{
    int i = blockIdx.x * 256 + threadIdx.x;
    if (i >= NQ * NPW) return;
    int j = i % NPW;
    float s = (j < 256) ? bp[j] : bw[j - 256];
#pragma unroll
    for (int z = 0; z < SPLITK; z++) s += part[(size_t)z * NQ * NPW + i];
    pw[i] = s;
}

// ------------------- deformable sampling + weighted sum --------------------
__global__ __launch_bounds__(256) void k_sample(const float* __restrict__ ref,
                                                const float* __restrict__ pw,
                                                const float* __restrict__ value,
                                                float* __restrict__ att)
{
    int q = blockIdx.x;
    int n = q / LQ;
    int t = threadIdx.x;
    int h = t >> 5, d = t & 31;
    __shared__ float s_px[NHEADS][16];
    __shared__ float s_py[NHEADS][16];
    __shared__ float s_w[NHEADS][16];
    __shared__ float s_ref[16];
    if (t < 16) s_ref[t] = ref[(size_t)q * 16 + t];
    __syncthreads();
    const float* row = pw + (size_t)q * NPW;
    if (t < 128) {
        int hh = t >> 4, lp = t & 15, l = lp >> 2;
        float ox = tanhf(row[2 * t]);
        float oy = tanhf(row[2 * t + 1]);
        s_px[hh][lp] = s_ref[l * 4 + 0] + ox * s_ref[l * 4 + 2] * 0.5f;
        s_py[hh][lp] = s_ref[l * 4 + 1] + oy * s_ref[l * 4 + 3] * 0.5f;
        s_w[hh][lp] = row[256 + t];
    }
    __syncthreads();
    if (t < NHEADS) {
        float mx = -1e30f;
#pragma unroll
        for (int i = 0; i < 16; i++) mx = fmaxf(mx, s_w[t][i]);
        float sum = 0.f;
#pragma unroll
        for (int i = 0; i < 16; i++) { float e = expf(s_w[t][i] - mx); s_w[t][i] = e; sum += e; }
        float inv = 1.f / sum;
#pragma unroll
        for (int i = 0; i < 16; i++) s_w[t][i] *= inv;
    }
    __syncthreads();
    const int HL[4] = {100, 50, 25, 13};
    const int WL[4] = {150, 75, 38, 19};
    const int SL[4] = {0, 15000, 18750, 19700};
    float acc = 0.f;
#pragma unroll
    for (int l = 0; l < NLVL; l++) {
        const float* base = value + ((size_t)n * LEN_IN + SL[l]) * CDIM + h * DH + d;
#pragma unroll
        for (int p = 0; p < NPTS; p++) {
            int lp = l * 4 + p;
            float px = s_px[h][lp] * (float)WL[l] - 0.5f;
            float py = s_py[h][lp] * (float)HL[l] - 0.5f;
            acc += s_w[h][lp] * bilin(base, HL[l], WL[l], CDIM, py, px);
        }
    }
    att[(size_t)q * CDIM + t] = acc;
}

// ------------------------------ launcher -----------------------------------
extern "C" void kernel_launch(void* const* d_in, const int* in_sizes, int n_in,
                              void* d_out, int out_size)
{
    (void)in_sizes; (void)n_in; (void)out_size;
    const float* ref  = (const float*)d_in[1];
    const float* flat = (const float*)d_in[2];
    const float* Wv   = (const float*)d_in[6];
    const float* bv   = (const float*)d_in[7];
    const float* Wp   = (const float*)d_in[8];
    const float* bp   = (const float*)d_in[9];
    const float* Ww   = (const float*)d_in[10];
    const float* bw   = (const float*)d_in[11];
    const float* Wo   = (const float*)d_in[12];
    const float* bo   = (const float*)d_in[13];
    float* out = (float*)d_out;

    float *p_value, *p_roi, *p_part, *p_pw, *p_att;
    __nv_bfloat16 *p_btv, *p_btpw;
    cudaGetSymbolAddress((void**)&p_value, g_value);
    cudaGetSymbolAddress((void**)&p_roi,   g_roi);
    cudaGetSymbolAddress((void**)&p_part,  g_part);
    cudaGetSymbolAddress((void**)&p_pw,    g_pw);
    cudaGetSymbolAddress((void**)&p_att,   g_att);
    cudaGetSymbolAddress((void**)&p_btv,   g_btv);
    cudaGetSymbolAddress((void**)&p_btpw,  g_btpw);

    cudaFuncSetAttribute(mma_gemm, cudaFuncAttributeMaxDynamicSharedMemorySize,
                         SM_BYTES);

    const int MV = NB * LEN_IN;                 // 79788

    // 0. pre-transpose + split weights to bf16 planes
    k_tsplit<<<dim3(CDIM / 32, CDIM / 32), 256>>>(
        Wv, CDIM, CDIM, p_btv, (size_t)CDIM * CDIM, 0);
    k_tsplit<<<dim3(256 / 32, ROI_DIM / 32), 256>>>(
        Wp, ROI_DIM, 256, p_btpw, (size_t)NPW * ROI_DIM, 0);
    k_tsplit<<<dim3(128 / 32, ROI_DIM / 32), 256>>>(
        Ww, ROI_DIM, 128, p_btpw, (size_t)NPW * ROI_DIM, 256);

    // 1. value = input_flatten @ Wv + bv   (grid 2 x 624)
    mma_gemm<<<dim3(CDIM / 128, (MV + 127) / 128, 1), 256, SM_BYTES>>>(
        flat, CDIM, p_btv, (size_t)CDIM * CDIM, CDIM,
        p_value, CDIM, 0, MV, CDIM, bv);

    // 2. ROI align on level-0 feature map
    k_roi<<<NQ, 256>>>(ref, p_value, p_roi);

    // 3. pw partials: roi_flat @ [Wp | Ww]^T-planes  (grid 3 x 10 x 14)
    mma_gemm<<<dim3(NPW / 128, (NQ + 127) / 128, SPLITK), 256, SM_BYTES>>>(
        p_roi, ROI_DIM, p_btpw, (size_t)NPW * ROI_DIM, ROI_DIM,
        p_part, NPW, (long long)NQ * NPW, NQ, KCHUNK, nullptr);
    k_reduce<<<(NQ * NPW + 255) / 256, 256>>>(p_part, bp, bw, p_pw);

    // 4. deformable sampling
    k_sample<<<NQ, 256>>>(ref, p_pw, p_value, p_att);

    // 5. out = att @ Wo + bo  (FFMA2, grid 2 x 10)
    sgemm128<<<dim3(CDIM / BN, (NQ + BM - 1) / BM, 1), 256>>>(
        p_att, CDIM, Wo, CDIM, out, CDIM, NQ, CDIM, bo);
}

// round 7
// speedup vs baseline: 1.7500x; 1.7500x over previous
#include <cuda_runtime.h>
#include <cuda_fp16.h>
#include <math.h>
#include <cstdint>

// ---------------------------------------------------------------------------
// MSMDDeformRegionAttn  (N=4, Lq=300, C=256, H=8, Dh=32, L=4, P=4, ROI=7)
//
//   1. value = input_flatten @ Wv + bv            (79788 x 256 x 256)  HMMA
//   2. ROI-align 7x7 on level-0 feature map -> roi planes (fp16 split)
//   3. pw = roi_flat @ [Wp | Ww]                  (1200 x 12544 x 384) HMMA
//   4. tanh offsets + softmax weights + deformable bilinear gather
//   5. out = att @ Wo + bo                        (1200 x 256 x 256)   HMMA
//
// All GEMMs: mma.sync m16n8k16 fp16 (baseline PTX) with 2-way fp16 split of
// each fp32 operand and 3 cross-products (00, 01, 10) -> residual ~2^-22.
// Weights pre-scaled x64 so residual terms stay in fp16 normal range;
// epilogue multiplies by 1/64. cp.async double-buffered, swizzled smem.
// ---------------------------------------------------------------------------

#define NBATCH  4
#define LQ      300
#define NQ      (NBATCH * LQ)      // 1200
#define CDIM    256
#define NHEADS  8
#define DH      32
#define NLVL    4
#define NPTS    4
#define ROI     7
#define LEN_IN  19947
#define ROI_DIM (ROI * ROI * CDIM) // 12544
#define NPW     384                // 256 (Wp) + 128 (Ww)
#define SPLITK  28
#define KCHUNK  (ROI_DIM / SPLITK) // 448 = 14 * 32
#define MV      (NBATCH * LEN_IN)  // 79788
#define MVPAD   79872              // 624 * 128
#define NQPAD   1280               // 10 * 128
#define WSCALE  64.0f
#define WSCALE_INV (1.0f / 64.0f)

// ------------------------- scratch (static device mem) ---------------------
__device__ float  g_value[(size_t)MV * CDIM];                  // 81.7 MB
__device__ __half g_aspl[(size_t)2 * MVPAD * CDIM];            // 81.8 MB
__device__ __half g_roiA[(size_t)2 * NQPAD * ROI_DIM];         // 64.2 MB
__device__ __half g_attA[(size_t)2 * NQPAD * CDIM];            //  1.3 MB
__device__ float  g_part[(size_t)SPLITK * NQ * NPW];           // 51.6 MB
__device__ float  g_pw[(size_t)NQ * NPW];
__device__ __half g_btv[(size_t)2 * CDIM * CDIM];
__device__ __half g_btpw[(size_t)2 * NPW * ROI_DIM];           // 19.3 MB
__device__ __half g_btwo[(size_t)2 * CDIM * CDIM];

// --------------------------- PTX primitives --------------------------------
__device__ __forceinline__ uint32_t smem_u32(const void* p)
{
    uint32_t a;
    asm("{ .reg .u64 t; cvta.to.shared.u64 t, %1; cvt.u32.u64 %0, t; }"
        : "=r"(a) : "l"(p));
    return a;
}
__device__ __forceinline__ void cp16(uint32_t dst, const void* src)
{
    asm volatile("cp.async.cg.shared.global [%0], [%1], 16;"
                 :: "r"(dst), "l"(src));
}
__device__ __forceinline__ void mma_f16(float* d, const uint32_t* a,
                                        const uint32_t* b)
{
    asm volatile(
        "mma.sync.aligned.m16n8k16.row.col.f32.f16.f16.f32 "
        "{%0,%1,%2,%3}, {%4,%5,%6,%7}, {%8,%9}, {%0,%1,%2,%3};"
        : "+f"(d[0]), "+f"(d[1]), "+f"(d[2]), "+f"(d[3])
        : "r"(a[0]), "r"(a[1]), "r"(a[2]), "r"(a[3]), "r"(b[0]), "r"(b[1]));
}
__device__ __forceinline__ void ldsm4(uint32_t* r, uint32_t addr)
{
    asm volatile(
        "ldmatrix.sync.aligned.m8n8.x4.shared.b16 {%0,%1,%2,%3}, [%4];"
        : "=r"(r[0]), "=r"(r[1]), "=r"(r[2]), "=r"(r[3]) : "r"(addr));
}

// --------------------------- fp16 2-way split -------------------------------
__device__ __forceinline__ void h2split(float x, __half& h0, __half& h1)
{
    h0 = __float2half_rn(x);
    h1 = __float2half_rn(x - __half2float(h0));
}

// ------------------------- fp16x2 HMMA GEMM ---------------------------------
// C = (A @ B^T) * outScale + bias, logical fp32 via 2-plane fp16 operands.
// A planes: Ap[p][m][k] (plane stride aPlane, row stride lda), m padded to 128.
// B planes: Bp[p][n][k] (plane stride bPlane, row stride ldb), n mult of 128.
// Block tile 128x128, BK=32, 8 warps (2x4), warp tile 64x32.
// Swizzled smem: row r (64B of 32 fp16), chunk c (16B): c' = c ^ ((r>>1)&3).
#define BUFB 32768   // bytes per buffer: A 2*8192 + B 2*8192
#define SMEM_TOT (2 * BUFB)

__global__ __launch_bounds__(256, 2) void mma_gemm(
    const __half* __restrict__ Ap, size_t aPlane, int lda,
    const __half* __restrict__ Bp, size_t bPlane, int ldb,
    float* __restrict__ C, int ldc, long long cSplitStride,
    int M, int kChunkTot, const float* __restrict__ bias, float outScale)
{
    extern __shared__ __align__(16) char smc[];
    const uint32_t sb = smem_u32(smc);
    const int tid = threadIdx.x, lane = tid & 31, wid = tid >> 5;
    const int warp_m = wid >> 2, warp_n = wid & 3;
    const int m0 = blockIdx.y * 128, n0 = blockIdx.x * 128;
    const int kBase = blockIdx.z * kChunkTot;
    C += (long long)blockIdx.z * cSplitStride;

    // cp.async coordinates: thread t -> rows lr, lr+64; 16B chunk lc
    const int lr = tid >> 2, lc = tid & 3;
    const uint32_t swz = (uint32_t)(lc ^ ((lr >> 1) & 3)) << 4;
    const uint32_t d1 = (uint32_t)lr * 64 + swz;
    const uint32_t d2 = d1 + 64 * 64;
    const __half* aS = Ap + (size_t)(m0 + lr) * lda + kBase + lc * 8;
    const __half* bS = Bp + (size_t)(n0 + lr) * ldb + kBase + lc * 8;

#define ISSUE(bo, ke)                                                          \
    do {                                                                       \
        cp16(sb + (bo) + d1, aS + (ke));                                       \
        cp16(sb + (bo) + 8192 + d1, aS + aPlane + (ke));                       \
        cp16(sb + (bo) + d2, aS + (size_t)64 * lda + (ke));                    \
        cp16(sb + (bo) + 8192 + d2, aS + aPlane + (size_t)64 * lda + (ke));    \
        cp16(sb + (bo) + 16384 + d1, bS + (ke));                               \
        cp16(sb + (bo) + 24576 + d1, bS + bPlane + (ke));                      \
        cp16(sb + (bo) + 16384 + d2, bS + (size_t)64 * ldb + (ke));            \
        cp16(sb + (bo) + 24576 + d2, bS + bPlane + (size_t)64 * ldb + (ke));   \
        asm volatile("cp.async.commit_group;" ::: "memory");                   \
    } while (0)

    // ldmatrix coordinates
    const uint32_t aRow = (uint32_t)(warp_m * 64 + (lane & 15));
    const uint32_t aOff = aRow * 64;
    const uint32_t aSwz = (aRow >> 1) & 3;
    const uint32_t aCk = (uint32_t)(lane >> 4);           // 0/1
    const uint32_t bRow = (uint32_t)(warp_n * 32 + ((lane >> 4) << 3) + (lane & 7));
    const uint32_t bOff = bRow * 64;
    const uint32_t bSwz = (bRow >> 1) & 3;
    const uint32_t bCk = (uint32_t)((lane >> 3) & 1);

    float acc[4][4][4];
#pragma unroll
    for (int i = 0; i < 4; i++)
#pragma unroll
        for (int j = 0; j < 4; j++)
#pragma unroll
            for (int e = 0; e < 4; e++) acc[i][j][e] = 0.f;

    const int nIter = kChunkTot / 32;
    ISSUE(0u, 0);
    uint32_t bo = 0;
    for (int it = 0; it < nIter; it++) {
        asm volatile("cp.async.wait_group 0;" ::: "memory");
        __syncthreads();
        if (it + 1 < nIter) ISSUE(bo ^ (uint32_t)BUFB, (it + 1) * 32);

        // compute buffer bo: 2 k16 steps x 3 plane-products x 16 mma
#pragma unroll
        for (int h = 0; h < 2; h++) {
            uint32_t bfr[2][4][2];
#pragma unroll
            for (int pb = 0; pb < 2; pb++)
#pragma unroll
                for (int jj = 0; jj < 2; jj++) {
                    uint32_t r[4];
                    ldsm4(r, sb + bo + 16384 + pb * 8192 + bOff + jj * 1024 +
                             ((((uint32_t)(h * 2) + bCk) ^ bSwz) << 4));
                    bfr[pb][jj * 2][0] = r[0]; bfr[pb][jj * 2][1] = r[1];
                    bfr[pb][jj * 2 + 1][0] = r[2]; bfr[pb][jj * 2 + 1][1] = r[3];
                }
#pragma unroll
            for (int pa = 0; pa < 2; pa++) {
                uint32_t af[4][4];
#pragma unroll
                for (int i = 0; i < 4; i++)
                    ldsm4(af[i], sb + bo + pa * 8192 + aOff + i * 1024 +
                                 ((((uint32_t)(h * 2) + aCk) ^ aSwz) << 4));
                const int npb = 2 - pa;   // pa=0: pb 0,1 ; pa=1: pb 0
                for (int pb = 0; pb < npb; pb++)
#pragma unroll
                    for (int i = 0; i < 4; i++)
#pragma unroll
                        for (int j = 0; j < 4; j++)
                            mma_f16(acc[i][j], af[i], bfr[pb][j]);
            }
        }
        bo ^= (uint32_t)BUFB;
    }
#undef ISSUE

    // epilogue
    const int colBase = n0 + warp_n * 32 + (lane & 3) * 2;
    const int rowBase = m0 + warp_m * 64 + (lane >> 2);
#pragma unroll
    for (int i = 0; i < 4; i++) {
#pragma unroll
        for (int j = 0; j < 4; j++) {
            const int gc = colBase + j * 8;
            float bx = 0.f, by = 0.f;
            if (bias) { bx = bias[gc]; by = bias[gc + 1]; }
            const int r0 = rowBase + i * 16;
            if (r0 < M) {
                float2 v = make_float2(acc[i][j][0] * outScale + bx,
                                       acc[i][j][1] * outScale + by);
                *(float2*)(C + (size_t)r0 * ldc + gc) = v;
            }
            const int r1 = r0 + 8;
            if (r1 < M) {
                float2 v = make_float2(acc[i][j][2] * outScale + bx,
                                       acc[i][j][3] * outScale + by);
                *(float2*)(C + (size_t)r1 * ldc + gc) = v;
            }
        }
    }
}

// -------------- weight transpose + scale(x64) + fp16 2-way split ------------
// W is [K][N] fp32; out planes are [Ntot][K] fp16, rows offset by rowOff.
__global__ __launch_bounds__(256) void k_tsplit(
    const float* __restrict__ W, int K, int N,
    __half* __restrict__ out, size_t plane, int rowOff)
{
    __shared__ float t[32][33];
    const int kb = blockIdx.y * 32, nb = blockIdx.x * 32;
    const int c = threadIdx.x & 31, r8 = threadIdx.x >> 5;
#pragma unroll
    for (int i = 0; i < 4; i++)
        t[r8 + i * 8][c] = W[(size_t)(kb + r8 + i * 8) * N + nb + c];
    __syncthreads();
#pragma unroll
    for (int i = 0; i < 4; i++) {
        const int n = nb + r8 + i * 8;
        const int k = kb + c;
        float x = t[c][r8 + i * 8] * WSCALE;
        __half h0, h1;
        h2split(x, h0, h1);
        size_t o = (size_t)(n + rowOff) * K + k;
        out[o] = h0;
        out[plane + o] = h1;
    }
}

// -------------------- A-operand fp16 2-way split (elementwise) --------------
__global__ __launch_bounds__(256) void k_asplit(
    const float* __restrict__ in, __half* __restrict__ out, size_t plane, int n4)
{
    int i = blockIdx.x * 256 + threadIdx.x;
    if (i >= n4) return;
    float4 v = ((const float4*)in)[i];
    float f[4] = {v.x, v.y, v.z, v.w};
    uint32_t p0[2], p1[2];
#pragma unroll
    for (int e = 0; e < 2; e++) {
        __half a0, a1, b0, b1;
        h2split(f[e * 2], a0, a1);
        h2split(f[e * 2 + 1], b0, b1);
        p0[e] = (uint32_t)__half_as_ushort(a0) |
                ((uint32_t)__half_as_ushort(b0) << 16);
        p1[e] = (uint32_t)__half_as_ushort(a1) |
                ((uint32_t)__half_as_ushort(b1) << 16);
    }
    *(uint2*)(out + (size_t)i * 4) = make_uint2(p0[0], p0[1]);
    *(uint2*)(out + plane + (size_t)i * 4) = make_uint2(p1[0], p1[1]);
}

// --------------------------- bilinear helper -------------------------------
__device__ __forceinline__ float bilin(const float* __restrict__ base,
                                       int Hl, int Wl, int stride,
                                       float y, float x)
{
    float fy = floorf(y), fx = floorf(x);
    int y0 = (int)fy, x0 = (int)fx;
    float wy1 = y - fy, wx1 = x - fx;
    float wy0 = 1.f - wy1, wx0 = 1.f - wx1;
    float v = 0.f;
    bool xa = (x0 >= 0) && (x0 < Wl);
    bool xb = (x0 + 1 >= 0) && (x0 + 1 < Wl);
    if (y0 >= 0 && y0 < Hl) {
        if (xa) v += base[(y0 * Wl + x0) * stride] * (wy0 * wx0);
        if (xb) v += base[(y0 * Wl + x0 + 1) * stride] * (wy0 * wx1);
    }
    if (y0 + 1 >= 0 && y0 + 1 < Hl) {
        if (xa) v += base[((y0 + 1) * Wl + x0) * stride] * (wy1 * wx0);
        if (xb) v += base[((y0 + 1) * Wl + x0 + 1) * stride] * (wy1 * wx1);
    }
    return v;
}

// ------------------- ROI align -> split fp16 planes -------------------------
__global__ __launch_bounds__(256) void k_roi(const float* __restrict__ ref,
                                             const float* __restrict__ value,
                                             __half* __restrict__ roiA)
{
    int q = blockIdx.x;
    int n = q / LQ;
    int t = threadIdx.x;
    __shared__ float sr[4];
    if (t < 4) sr[t] = ref[(size_t)q * 16 + t];
    __syncthreads();
    const float cx = sr[0], cy = sr[1], w = sr[2], h = sr[3];
    const float x1 = (cx - 0.5f * w) * 150.f - 0.5f;
    const float y1 = (cy - 0.5f * h) * 100.f - 0.5f;
    const float bw = w * 150.f / (float)ROI;
    const float bh = h * 100.f / (float)ROI;
    const float* base = value + (size_t)n * LEN_IN * CDIM + t;
    __half* out0 = roiA + (size_t)q * ROI_DIM;
    __half* out1 = out0 + (size_t)NQPAD * ROI_DIM;
    for (int by = 0; by < ROI; by++) {
        float y = y1 + bh * ((float)by + 0.5f);
        for (int bx = 0; bx < ROI; bx++) {
            float x = x1 + bw * ((float)bx + 0.5f);
            float v = bilin(base, 100, 150, CDIM, y, x);
            __half h0, h1;
            h2split(v, h0, h1);
            out0[(by * ROI + bx) * CDIM + t] = h0;
            out1[(by * ROI + bx) * CDIM + t] = h1;
        }
    }
}

// ------------------------- split-K reduce + bias ----------------------------
__global__ __launch_bounds__(256) void k_reduce(const float* __restrict__ part,
                                                const float* __restrict__ bp,
                                                const float* __restrict__ bw,
                                                float* __restrict__ pw)
{
    int i = blockIdx.x * 256 + threadIdx.x;
    if (i >= NQ * NPW) return;
    int j = i % NPW;
    float s = (j < 256) ? bp[j] : bw[j - 256];
#pragma unroll
    for (int z = 0; z < SPLITK; z++) s += part[(size_t)z * NQ * NPW + i];
    pw[i] = s;
}

// -------- deformable sampling + weighted sum -> split fp16 att planes -------
__global__ __launch_bounds__(256) void k_sample(const float* __restrict__ ref,
                                                const float* __restrict__ pw,
                                                const float* __restrict__ value,
                                                __half* __restrict__ attA)
{
    int q = blockIdx.x;
    int n = q / LQ;
    int t = threadIdx.x;
    int h = t >> 5, d = t & 31;
    __shared__ float s_px[NHEADS][16];
    __shared__ float s_py[NHEADS][16];
    __shared__ float s_w[NHEADS][16];
    __shared__ float s_ref[16];
    if (t < 16) s_ref[t] = ref[(size_t)q * 16 + t];
    __syncthreads();
    const float* row = pw + (size_t)q * NPW;
    if (t < 128) {
        int hh = t >> 4, lp = t & 15, l = lp >> 2;
        float ox = tanhf(row[2 * t]);
        float oy = tanhf(row[2 * t + 1]);
        s_px[hh][lp] = s_ref[l * 4 + 0] + ox * s_ref[l * 4 + 2] * 0.5f;
        s_py[hh][lp] = s_ref[l * 4 + 1] + oy * s_ref[l * 4 + 3] * 0.5f;
        s_w[hh][lp] = row[256 + t];
    }
    __syncthreads();
    if (t < NHEADS) {
        float mx = -1e30f;
#pragma unroll
        for (int i = 0; i < 16; i++) mx = fmaxf(mx, s_w[t][i]);
        float sum = 0.f;
#pragma unroll
        for (int i = 0; i < 16; i++) {
            float e = expf(s_w[t][i] - mx);
            s_w[t][i] = e;
            sum += e;
        }
        float inv = 1.f / sum;
#pragma unroll
        for (int i = 0; i < 16; i++) s_w[t][i] *= inv;
    }
    __syncthreads();
    const int HL[4] = {100, 50, 25, 13};
    const int WL[4] = {150, 75, 38, 19};
    const int SL[4] = {0, 15000, 18750, 19700};
    float acc = 0.f;
#pragma unroll
    for (int l = 0; l < NLVL; l++) {
        const float* base =
            value + ((size_t)n * LEN_IN + SL[l]) * CDIM + h * DH + d;
#pragma unroll
        for (int p = 0; p < NPTS; p++) {
            int lp = l * 4 + p;
            float px = s_px[h][lp] * (float)WL[l] - 0.5f;
            float py = s_py[h][lp] * (float)HL[l] - 0.5f;
            acc += s_w[h][lp] * bilin(base, HL[l], WL[l], CDIM, py, px);
        }
    }
    __half h0, h1;
    h2split(acc, h0, h1);
    attA[(size_t)q * CDIM + t] = h0;
    attA[(size_t)NQPAD * CDIM + (size_t)q * CDIM + t] = h1;
}

// ------------------------------ launcher -----------------------------------
extern "C" void kernel_launch(void* const* d_in, const int* in_sizes, int n_in,
                              void* d_out, int out_size)
{
    (void)in_sizes; (void)n_in; (void)out_size;
    const float* ref  = (const float*)d_in[1];
    const float* flat = (const float*)d_in[2];
    const float* Wv   = (const float*)d_in[6];
    const float* bv   = (const float*)d_in[7];
    const float* Wp   = (const float*)d_in[8];
    const float* bp   = (const float*)d_in[9];
    const float* Ww   = (const float*)d_in[10];
    const float* bw   = (const float*)d_in[11];
    const float* Wo   = (const float*)d_in[12];
    const float* bo   = (const float*)d_in[13];
    float* out = (float*)d_out;

    float *p_value, *p_part, *p_pw;
    __half *p_aspl, *p_roiA, *p_attA, *p_btv, *p_btpw, *p_btwo;
    cudaGetSymbolAddress((void**)&p_value, g_value);
    cudaGetSymbolAddress((void**)&p_aspl,  g_aspl);
    cudaGetSymbolAddress((void**)&p_roiA,  g_roiA);
    cudaGetSymbolAddress((void**)&p_attA,  g_attA);
    cudaGetSymbolAddress((void**)&p_part,  g_part);
    cudaGetSymbolAddress((void**)&p_pw,    g_pw);
    cudaGetSymbolAddress((void**)&p_btv,   g_btv);
    cudaGetSymbolAddress((void**)&p_btpw,  g_btpw);
    cudaGetSymbolAddress((void**)&p_btwo,  g_btwo);

    cudaFuncSetAttribute(mma_gemm, cudaFuncAttributeMaxDynamicSharedMemorySize,
                         SMEM_TOT);

    // 0. weight transpose + x64 scale + fp16 split
    k_tsplit<<<dim3(CDIM / 32, CDIM / 32), 256>>>(
        Wv, CDIM, CDIM, p_btv, (size_t)CDIM * CDIM, 0);
    k_tsplit<<<dim3(256 / 32, ROI_DIM / 32), 256>>>(
        Wp, ROI_DIM, 256, p_btpw, (size_t)NPW * ROI_DIM, 0);
    k_tsplit<<<dim3(128 / 32, ROI_DIM / 32), 256>>>(
        Ww, ROI_DIM, 128, p_btpw, (size_t)NPW * ROI_DIM, 256);
    k_tsplit<<<dim3(CDIM / 32, CDIM / 32), 256>>>(
        Wo, CDIM, CDIM, p_btwo, (size_t)CDIM * CDIM, 0);

    // 0b. split input_flatten into fp16 planes
    const int n4 = MV * CDIM / 4;
    k_asplit<<<(n4 + 255) / 256, 256>>>(flat, p_aspl,
                                        (size_t)MVPAD * CDIM, n4);

    // 1. value = input_flatten @ Wv + bv   (grid 2 x 624)
    mma_gemm<<<dim3(CDIM / 128, MVPAD / 128, 1), 256, SMEM_TOT>>>(
        p_aspl, (size_t)MVPAD * CDIM, CDIM,
        p_btv, (size_t)CDIM * CDIM, CDIM,
        p_value, CDIM, 0, MV, CDIM, bv, WSCALE_INV);

    // 2. ROI align -> split fp16 roi planes
    k_roi<<<NQ, 256>>>(ref, p_value, p_roiA);

    // 3. pw partials: roi @ [Wp | Ww]  (grid 3 x 10 x 28)
    mma_gemm<<<dim3(NPW / 128, NQPAD / 128, SPLITK), 256, SMEM_TOT>>>(
        p_roiA, (size_t)NQPAD * ROI_DIM, ROI_DIM,
        p_btpw, (size_t)NPW * ROI_DIM, ROI_DIM,
        p_part, NPW, (long long)NQ * NPW, NQ, KCHUNK, nullptr, WSCALE_INV);
    k_reduce<<<(NQ * NPW + 255) / 256, 256>>>(p_part, bp, bw, p_pw);

    // 4. deformable sampling -> split fp16 att planes
    k_sample<<<NQ, 256>>>(ref, p_pw, p_value, p_attA);

    // 5. out = att @ Wo + bo  (grid 2 x 10)
    mma_gemm<<<dim3(CDIM / 128, NQPAD / 128, 1), 256, SMEM_TOT>>>(
        p_attA, (size_t)NQPAD * CDIM, CDIM,
        p_btwo, (size_t)CDIM * CDIM, CDIM,
        out, CDIM, 0, NQ, CDIM, bo, WSCALE_INV);
}